// round 11
// baseline (speedup 1.0000x reference)
#include <cuda_runtime.h>
#include <cuda_fp16.h>
#include <cstdint>

// Problem constants (from reference)
#define N_ATOMS   100000
#define N_PAIRS   6400000
#define NS        119
#define R_MAX     6.0f
#define PI_F      3.14159265358979323846f
#define LOG2E_F   1.4426950408889634f

#define THREADS   256
#define UNROLL    2
#define PAIRS_PER_BLOCK (THREADS * UNROLL)             // 512
#define NBLK      (N_PAIRS / PAIRS_PER_BLOCK)          // 12500 (exact)

#define TAB_BLOCKS ((NS * NS + 255) / 256)             // 56
#define PACK_BLOCKS ((N_ATOMS + 255) / 256)            // 391

// -------- device scratch (no allocations allowed) --------
// Single 32B entry per (Zi,Zj): one L2 sector, two LDG.128.
//   q0 = { bits(half2{pc0,pc1}), bits(half2{pc2,pe0}), bits(half2{pe1,pe2}), De }
//   q1 = { p1, p2, rinv, pad }
struct __align__(32) Tab {
    float4 q0;
    float4 q1;
};
__device__ float4 g_RZ[N_ATOMS];              // {x, y, z, as_float(Z)}
__device__ Tab    g_tab[NS * NS];             // 453 KB
__device__ float  g_partial[NBLK];

// Fast MUFU ops via PTX (single instruction regardless of compile flags)
__device__ __forceinline__ float fex2(float x) {
    float y; asm("ex2.approx.ftz.f32 %0, %1;" : "=f"(y) : "f"(x)); return y;
}
__device__ __forceinline__ float flg2(float x) {
    float y; asm("lg2.approx.ftz.f32 %0, %1;" : "=f"(y) : "f"(x)); return y;
}
__device__ __forceinline__ float frsq(float x) {
    float y; asm("rsqrt.approx.ftz.f32 %0, %1;" : "=f"(y) : "f"(x)); return y;
}

// softplus, matches jax.nn.softplus numerics: relu(x) + log1p(exp(-|x|))
__device__ __forceinline__ float sp(float x) {
    return fmaxf(x, 0.0f) + log1pf(expf(-fabsf(x)));
}

__device__ __forceinline__ float2 h2f(float bits) {
    return __half22float2(*reinterpret_cast<const __half2*>(&bits));
}

// -------- kernel 1: build table + pack RZ (fused) --------
__global__ void prep_kernel(const float* __restrict__ R,
                            const int* __restrict__ Z,
                            const float* __restrict__ r0,
                            const float* __restrict__ po_coeff,
                            const float* __restrict__ po_exp,
                            const float* __restrict__ De,
                            const float* __restrict__ pbe1,
                            const float* __restrict__ pbe2) {
    if (blockIdx.x < TAB_BLOCKS) {
        int e = blockIdx.x * blockDim.x + threadIdx.x;
        if (e >= NS * NS) return;
        int zi = e / NS;
        int zj = e - zi * NS;

        float pc0 = sp(po_coeff[e * 3 + 0]);
        float pc1 = sp(po_coeff[e * 3 + 1]);
        float pc2 = sp(po_coeff[e * 3 + 2]);
        float pe0 = sp(po_exp[e * 3 + 0]);
        float pe1 = sp(po_exp[e * 3 + 1]);
        float pe2 = sp(po_exp[e * 3 + 2]);

        __half2 h01 = __floats2half2_rn(pc0, pc1);
        __half2 h2e = __floats2half2_rn(pc2, pe0);
        __half2 h12 = __floats2half2_rn(pe1, pe2);

        Tab t;
        t.q0.x = *reinterpret_cast<const float*>(&h01);
        t.q0.y = *reinterpret_cast<const float*>(&h2e);
        t.q0.z = *reinterpret_cast<const float*>(&h12);
        t.q0.w = sp(De[e]);
        float r0ij = 0.5f * (sp(r0[zi]) + sp(r0[zj]));
        t.q1 = make_float4(pbe1[e], sp(pbe2[e] + 1.0f), 1.0f / r0ij, 0.0f);
        g_tab[e] = t;
    } else {
        int i = (blockIdx.x - TAB_BLOCKS) * blockDim.x + threadIdx.x;
        if (i >= N_ATOMS) return;
        g_RZ[i] = make_float4(R[3 * i + 0], R[3 * i + 1], R[3 * i + 2],
                              __int_as_float(Z[i]));
    }
}

// -------- warp/block reduction helper --------
__device__ __forceinline__ float warp_sum(float v) {
    #pragma unroll
    for (int o = 16; o > 0; o >>= 1)
        v += __shfl_down_sync(0xffffffffu, v, o);
    return v;
}

// -------- kernel 2: main pair kernel, 2 pairs/thread --------
__global__ void __launch_bounds__(THREADS)
pair_kernel(const int* __restrict__ idx) {
    int t = blockIdx.x * blockDim.x + threadIdx.x;   // always < N_PAIRS/2

    // coalesced int2 loads: 2 pair indices per stream
    int2 iv = reinterpret_cast<const int2*>(idx)[t];
    int2 jv = reinterpret_cast<const int2*>(idx + N_PAIRS)[t];
    int ii[UNROLL] = {iv.x, iv.y};
    int jj[UNROLL] = {jv.x, jv.y};

    // front-batched RZ gathers (4 independent LDG.128)
    float4 A[UNROLL], B[UNROLL];
    #pragma unroll
    for (int k = 0; k < UNROLL; k++) {
        A[k] = g_RZ[ii[k]];
        B[k] = g_RZ[jj[k]];
    }

    // batched table loads: 2 LDG.128 per pair, same 32B sector
    float4 Q0[UNROLL], Q1[UNROLL];
    #pragma unroll
    for (int k = 0; k < UNROLL; k++) {
        int e = __float_as_int(A[k].w) * NS + __float_as_int(B[k].w);
        Q0[k] = g_tab[e].q0;
        Q1[k] = g_tab[e].q1;
    }

    float E = 0.0f;
    #pragma unroll
    for (int k = 0; k < UNROLL; k++) {
        float dx = B[k].x - A[k].x;
        float dy = B[k].y - A[k].y;
        float dz = B[k].z - A[k].z;
        float d2 = fmaf(dx, dx, fmaf(dy, dy, dz * dz));
        bool pos = d2 > 0.0f;
        float dr = pos ? d2 * frsq(d2) : 0.0f;
        float drc = fminf(dr, R_MAX);
        float cut = 0.5f * (__cosf(drc * (PI_F / R_MAX)) + 1.0f);

        // unpack fp16 pc/pe
        float2 pc01 = h2f(Q0[k].x);       // pc0, pc1
        float2 pc2e = h2f(Q0[k].y);       // pc2, pe0
        float2 pe12 = h2f(Q0[k].z);       // pe1, pe2
        float De_ij = Q0[k].w;
        float p1v   = Q1[k].x;
        float p2v   = Q1[k].y;
        float rinv  = Q1[k].z;

        float ratio = dr * rinv;
        float L = flg2(ratio);                 // -inf when dr == 0
        float t0 = fex2(pc2e.y * L);
        float t1 = fex2(pe12.x * L);
        float t2 = fex2(pe12.y * L);
        if (!pos) { t0 = 0.0f; t1 = 0.0f; t2 = 0.0f; }   // safe_pow limit

        float e0 = fex2(-LOG2E_F * pc01.x * t0);
        float e1 = fex2(-LOG2E_F * pc01.y * t1);
        float e2 = fex2(-LOG2E_F * pc2e.x * t2);
        float bo = cut * (e0 + e1 + e2);

        float bp = (bo > 0.0f) ? fex2(p2v * flg2(bo)) : 0.0f;
        float ef = fex2(LOG2E_F * p1v * (1.0f - bp));
        float Ek = -De_ij * bo * ef;
        E += (ii[k] != jj[k]) ? Ek : 0.0f;     // mask padded / self pairs
    }

    // block reduction to partials (deterministic, no fences/atomics)
    __shared__ float sh[THREADS / 32];
    float v = warp_sum(E);
    int lane = threadIdx.x & 31;
    int wid  = threadIdx.x >> 5;
    if (lane == 0) sh[wid] = v;
    __syncthreads();
    if (wid == 0) {
        v = (lane < (THREADS / 32)) ? sh[lane] : 0.0f;
        v = warp_sum(v);
        if (lane == 0) g_partial[blockIdx.x] = v;
    }
}

// -------- kernel 3: final deterministic reduction (vectorized) --------
__global__ void __launch_bounds__(1024)
reduce_kernel(float* __restrict__ out) {
    const float4* p4 = reinterpret_cast<const float4*>(g_partial);
    float s = 0.0f;
    for (int i = threadIdx.x; i < NBLK / 4; i += 1024) {
        float4 v = p4[i];
        s += (v.x + v.y) + (v.z + v.w);
    }
    __shared__ float sh[32];
    float v = warp_sum(s);
    int lane = threadIdx.x & 31;
    int wid  = threadIdx.x >> 5;
    if (lane == 0) sh[wid] = v;
    __syncthreads();
    if (wid == 0) {
        v = (lane < 32) ? sh[lane] : 0.0f;
        v = warp_sum(v);
        if (lane == 0) out[0] = v;
    }
}

extern "C" void kernel_launch(void* const* d_in, const int* in_sizes, int n_in,
                              void* d_out, int out_size) {
    const float* R        = (const float*)d_in[0];
    const int*   Z        = (const int*)  d_in[1];
    const int*   idx      = (const int*)  d_in[2];
    const float* r0       = (const float*)d_in[3];
    const float* po_coeff = (const float*)d_in[4];
    const float* po_exp   = (const float*)d_in[5];
    const float* De       = (const float*)d_in[6];
    const float* pbe1     = (const float*)d_in[7];
    const float* pbe2     = (const float*)d_in[8];
    float* out = (float*)d_out;

    prep_kernel<<<TAB_BLOCKS + PACK_BLOCKS, 256>>>(R, Z, r0, po_coeff, po_exp,
                                                   De, pbe1, pbe2);
    pair_kernel<<<NBLK, THREADS>>>(idx);
    reduce_kernel<<<1, 1024>>>(out);
}

// round 12
// speedup vs baseline: 1.3325x; 1.3325x over previous
#include <cuda_runtime.h>
#include <cstdint>

// Problem constants (from reference)
#define N_ATOMS   100000
#define N_PAIRS   6400000
#define NS        119
#define R_MAX     6.0f
#define PI_F      3.14159265358979323846f
#define LOG2E_F   1.4426950408889634f

#define THREADS   256
#define UNROLL    2
#define PAIRS_PER_BLOCK (THREADS * UNROLL)             // 512
#define NBLK      (N_PAIRS / PAIRS_PER_BLOCK)          // 12500 (exact)

#define TAB_BLOCKS ((NS * NS + 255) / 256)             // 56
#define PACK_BLOCKS ((N_ATOMS + 255) / 256)            // 391

// -------- device scratch (no allocations allowed) --------
// 32B-aligned table entry -> exactly one L2 sector per gather
struct __align__(32) TabA {
    float4 a;   // {pc0, pc1, pc2, pe0}
    float4 b;   // {pe1, pe2, De,  p1 }
};
__device__ float4 g_RZ[N_ATOMS];              // {x, y, z, as_float(Z)}
__device__ TabA   g_tabA[NS * NS];            // 453 KB (1 sector/entry)
__device__ float2 g_tabB[NS * NS];            // {p2, rinv} 113 KB -> L1-resident
__device__ float  g_partial[NBLK];

// Fast MUFU ops via PTX (single instruction regardless of compile flags)
__device__ __forceinline__ float fex2(float x) {
    float y; asm("ex2.approx.ftz.f32 %0, %1;" : "=f"(y) : "f"(x)); return y;
}
__device__ __forceinline__ float flg2(float x) {
    float y; asm("lg2.approx.ftz.f32 %0, %1;" : "=f"(y) : "f"(x)); return y;
}
__device__ __forceinline__ float frsq(float x) {
    float y; asm("rsqrt.approx.ftz.f32 %0, %1;" : "=f"(y) : "f"(x)); return y;
}

// softplus, matches jax.nn.softplus numerics: relu(x) + log1p(exp(-|x|))
__device__ __forceinline__ float sp(float x) {
    return fmaxf(x, 0.0f) + log1pf(expf(-fabsf(x)));
}

// -------- kernel 1: build tables + pack RZ (fused, one launch) --------
__global__ void prep_kernel(const float* __restrict__ R,
                            const int* __restrict__ Z,
                            const float* __restrict__ r0,
                            const float* __restrict__ po_coeff,
                            const float* __restrict__ po_exp,
                            const float* __restrict__ De,
                            const float* __restrict__ pbe1,
                            const float* __restrict__ pbe2) {
    if (blockIdx.x < TAB_BLOCKS) {
        int e = blockIdx.x * blockDim.x + threadIdx.x;
        if (e >= NS * NS) return;
        int zi = e / NS;
        int zj = e - zi * NS;

        TabA ta;
        ta.a.x = sp(po_coeff[e * 3 + 0]);
        ta.a.y = sp(po_coeff[e * 3 + 1]);
        ta.a.z = sp(po_coeff[e * 3 + 2]);
        ta.a.w = sp(po_exp[e * 3 + 0]);
        ta.b.x = sp(po_exp[e * 3 + 1]);
        ta.b.y = sp(po_exp[e * 3 + 2]);
        ta.b.z = sp(De[e]);
        ta.b.w = pbe1[e];
        g_tabA[e] = ta;

        float r0ij = 0.5f * (sp(r0[zi]) + sp(r0[zj]));
        g_tabB[e] = make_float2(sp(pbe2[e] + 1.0f), 1.0f / r0ij);
    } else {
        int i = (blockIdx.x - TAB_BLOCKS) * blockDim.x + threadIdx.x;
        if (i >= N_ATOMS) return;
        g_RZ[i] = make_float4(R[3 * i + 0], R[3 * i + 1], R[3 * i + 2],
                              __int_as_float(Z[i]));
    }
}

// -------- warp/block reduction helper --------
__device__ __forceinline__ float warp_sum(float v) {
    #pragma unroll
    for (int o = 16; o > 0; o >>= 1)
        v += __shfl_down_sync(0xffffffffu, v, o);
    return v;
}

// -------- kernel 2: main pair kernel, 2 pairs/thread (R7 hot loop, unchanged) --------
__global__ void __launch_bounds__(THREADS)
pair_kernel(const int* __restrict__ idx) {
    int t = blockIdx.x * blockDim.x + threadIdx.x;   // always < N_PAIRS/2

    // coalesced int2 loads: 2 pair indices per stream
    int2 iv = reinterpret_cast<const int2*>(idx)[t];
    int2 jv = reinterpret_cast<const int2*>(idx + N_PAIRS)[t];
    int ii[UNROLL] = {iv.x, iv.y};
    int jj[UNROLL] = {jv.x, jv.y};

    // front-batched RZ gathers (4 independent LDG.128)
    float4 A[UNROLL], B[UNROLL];
    #pragma unroll
    for (int k = 0; k < UNROLL; k++) {
        A[k] = g_RZ[ii[k]];
        B[k] = g_RZ[jj[k]];
    }

    // batched table loads (tabA: 1 sector each; tabB: L1-resident)
    float4 QA[UNROLL], QB[UNROLL];
    float2 QC[UNROLL];
    #pragma unroll
    for (int k = 0; k < UNROLL; k++) {
        int e = __float_as_int(A[k].w) * NS + __float_as_int(B[k].w);
        QA[k] = g_tabA[e].a;
        QB[k] = g_tabA[e].b;
        QC[k] = g_tabB[e];
    }

    float E = 0.0f;
    #pragma unroll
    for (int k = 0; k < UNROLL; k++) {
        float dx = B[k].x - A[k].x;
        float dy = B[k].y - A[k].y;
        float dz = B[k].z - A[k].z;
        float d2 = fmaf(dx, dx, fmaf(dy, dy, dz * dz));
        bool pos = d2 > 0.0f;
        float dr = pos ? d2 * frsq(d2) : 0.0f;
        float drc = fminf(dr, R_MAX);
        float cut = 0.5f * (__cosf(drc * (PI_F / R_MAX)) + 1.0f);

        float ratio = dr * QC[k].y;
        float L = flg2(ratio);                 // -inf when dr == 0
        float t0 = fex2(QA[k].w * L);
        float t1 = fex2(QB[k].x * L);
        float t2 = fex2(QB[k].y * L);
        if (!pos) { t0 = 0.0f; t1 = 0.0f; t2 = 0.0f; }   // safe_pow limit

        float e0 = fex2(-LOG2E_F * QA[k].x * t0);
        float e1 = fex2(-LOG2E_F * QA[k].y * t1);
        float e2 = fex2(-LOG2E_F * QA[k].z * t2);
        float bo = cut * (e0 + e1 + e2);

        float bp = (bo > 0.0f) ? fex2(QC[k].x * flg2(bo)) : 0.0f;
        float ef = fex2(LOG2E_F * QB[k].w * (1.0f - bp));
        float Ek = -QB[k].z * bo * ef;
        E += (ii[k] != jj[k]) ? Ek : 0.0f;     // mask padded / self pairs
    }

    // block reduction to partials (deterministic, no fences/atomics)
    __shared__ float sh[THREADS / 32];
    float v = warp_sum(E);
    int lane = threadIdx.x & 31;
    int wid  = threadIdx.x >> 5;
    if (lane == 0) sh[wid] = v;
    __syncthreads();
    if (wid == 0) {
        v = (lane < (THREADS / 32)) ? sh[lane] : 0.0f;
        v = warp_sum(v);
        if (lane == 0) g_partial[blockIdx.x] = v;
    }
}

// -------- kernel 3: final deterministic reduction (vectorized float4) --------
__global__ void __launch_bounds__(1024)
reduce_kernel(float* __restrict__ out) {
    const float4* p4 = reinterpret_cast<const float4*>(g_partial);
    float s = 0.0f;
    for (int i = threadIdx.x; i < NBLK / 4; i += 1024) {   // 12500/4 = 3125
        float4 v = p4[i];
        s += (v.x + v.y) + (v.z + v.w);
    }
    __shared__ float sh[32];
    float v = warp_sum(s);
    int lane = threadIdx.x & 31;
    int wid  = threadIdx.x >> 5;
    if (lane == 0) sh[wid] = v;
    __syncthreads();
    if (wid == 0) {
        v = (lane < 32) ? sh[lane] : 0.0f;
        v = warp_sum(v);
        if (lane == 0) out[0] = v;
    }
}

extern "C" void kernel_launch(void* const* d_in, const int* in_sizes, int n_in,
                              void* d_out, int out_size) {
    const float* R        = (const float*)d_in[0];
    const int*   Z        = (const int*)  d_in[1];
    const int*   idx      = (const int*)  d_in[2];
    const float* r0       = (const float*)d_in[3];
    const float* po_coeff = (const float*)d_in[4];
    const float* po_exp   = (const float*)d_in[5];
    const float* De       = (const float*)d_in[6];
    const float* pbe1     = (const float*)d_in[7];
    const float* pbe2     = (const float*)d_in[8];
    float* out = (float*)d_out;

    prep_kernel<<<TAB_BLOCKS + PACK_BLOCKS, 256>>>(R, Z, r0, po_coeff, po_exp,
                                                   De, pbe1, pbe2);
    pair_kernel<<<NBLK, THREADS>>>(idx);
    reduce_kernel<<<1, 1024>>>(out);
}